// round 17
// baseline (speedup 1.0000x reference)
#include <cuda_runtime.h>
#include <cstdint>

// ============================================================================
// out[4096,4096] = ((x - xz)*sx) @ ((y - yz)*sy)
// Exact int8 GEMM + rank-1 zero-point correction.
// tcgen05 unavailable (harness lowers PTX to compute_103, non-'a').
// R16: 64/64 hybrid split into 2 CTAs/SM (CTA tile 128x64, 256 thr,
//      4 tensor + 4 dp4a warps, 3-stage pipeline) so the two CTAs hide each
//      other's barrier/epilogue bubbles (~1350 cyc/step exposed in R12).
// ============================================================================

#define MDIM 4096

static constexpr double X_SCALE = 0.03, X_ZP = -66.0;
static constexpr double Y_SCALE = 0.025, Y_ZP = 160.0;

// GEMM tiling
static constexpr int BM = 128, BN = 64, BK = 128, STAGES = 3;
static constexpr int BN_T = 32;                       // tensor columns
static constexpr int ROWB = 144;                      // 128B data + 16B pad
static constexpr int A_STAGE = BM * ROWB;             // 18432
static constexpr int B_STAGE = BN * ROWB;             // 9216
static constexpr int STAGE_BYTES = A_STAGE + B_STAGE; // 27648
static constexpr int SMEM_TOTAL = STAGES * STAGE_BYTES; // 82944 (x2 CTAs/SM)
static constexpr int NT_N = MDIM / BN;                // 64
static constexpr int NTILES = (MDIM / BM) * NT_N;     // 2048
static constexpr int KITER = MDIM / BK;               // 32

// Scratch (device globals: allocation-free per harness rules)
__device__ char  g_x8 [(size_t)MDIM * MDIM];  // x as s8 (exact)
__device__ char  g_y8t[(size_t)MDIM * MDIM];  // (y-128)^T as s8, [N,K]
__device__ float g_rowsum[MDIM];              // sum_k x[m,k]        (exact int)
__device__ float g_colsum[MDIM];              // sum_k (y[k,n]-128)  (exact int)

// ---------------------------------------------------------------------------
// PTX helpers
// ---------------------------------------------------------------------------
__device__ __forceinline__ uint32_t smem_u32(const void* p) {
    uint32_t a;
    asm("{ .reg .u64 t; cvta.to.shared.u64 t, %1; cvt.u32.u64 %0, t; }"
        : "=r"(a) : "l"(p));
    return a;
}
__device__ __forceinline__ void cp_async16(uint32_t s, const void* g) {
    asm volatile("cp.async.cg.shared.global [%0], [%1], 16;" :: "r"(s), "l"(g));
}
#define CP_COMMIT() asm volatile("cp.async.commit_group;")
#define CP_WAIT1()  asm volatile("cp.async.wait_group 1;")

__device__ __forceinline__ void ldmatrix_x4(uint32_t* r, uint32_t addr) {
    asm volatile("ldmatrix.sync.aligned.m8n8.x4.shared.b16 {%0,%1,%2,%3}, [%4];"
                 : "=r"(r[0]), "=r"(r[1]), "=r"(r[2]), "=r"(r[3]) : "r"(addr));
}
__device__ __forceinline__ void mma_s8(int* d, const uint32_t* a, const uint32_t* b) {
    asm volatile(
        "mma.sync.aligned.m16n8k32.row.col.s32.s8.s8.s32 "
        "{%0,%1,%2,%3}, {%4,%5,%6,%7}, {%8,%9}, {%0,%1,%2,%3};"
        : "+r"(d[0]), "+r"(d[1]), "+r"(d[2]), "+r"(d[3])
        : "r"(a[0]), "r"(a[1]), "r"(a[2]), "r"(a[3]), "r"(b[0]), "r"(b[1]));
}

// ---------------------------------------------------------------------------
// Preprocessing (unchanged from R8/R12-passing)
// ---------------------------------------------------------------------------
__global__ __launch_bounds__(256) void convert_x_kernel(const float* __restrict__ x) {
    int row = blockIdx.x;
    const float4* xr = (const float4*)(x + (size_t)row * MDIM);
    uchar4* xo = (uchar4*)(g_x8 + (size_t)row * MDIM);
    float s = 0.f;
#pragma unroll
    for (int q = 0; q < 4; q++) {
        int i = q * 256 + threadIdx.x;
        float4 v = xr[i];
        s += (v.x + v.y) + (v.z + v.w);
        uchar4 o;
        o.x = (unsigned char)(int)v.x;
        o.y = (unsigned char)(int)v.y;
        o.z = (unsigned char)(int)v.z;
        o.w = (unsigned char)(int)v.w;
        xo[i] = o;
    }
    __shared__ float red[256];
    red[threadIdx.x] = s;
    __syncthreads();
    for (int st = 128; st > 0; st >>= 1) {
        if (threadIdx.x < st) red[threadIdx.x] += red[threadIdx.x + st];
        __syncthreads();
    }
    if (threadIdx.x == 0) g_rowsum[row] = red[0];
}

__global__ __launch_bounds__(256) void transpose_y_kernel(const float* __restrict__ y) {
    __shared__ float tile[64][65];
    int n0 = blockIdx.x * 64, k0 = blockIdx.y * 64;
    int tid = threadIdx.x;
    int col = tid & 63, r4 = tid >> 6;
#pragma unroll
    for (int p = 0; p < 16; p++) {
        int row = p * 4 + r4;
        tile[row][col] = y[(size_t)(k0 + row) * MDIM + n0 + col];
    }
    __syncthreads();
    int n = tid >> 2, kc = tid & 3;
    uchar4 o[4];
    int part = 0;
#pragma unroll
    for (int q = 0; q < 4; q++) {
        int k = kc * 16 + q * 4;
        int v0 = (int)tile[k + 0][n] - 128, v1 = (int)tile[k + 1][n] - 128;
        int v2 = (int)tile[k + 2][n] - 128, v3 = (int)tile[k + 3][n] - 128;
        part += v0 + v1 + v2 + v3;
        o[q].x = (unsigned char)v0; o[q].y = (unsigned char)v1;
        o[q].z = (unsigned char)v2; o[q].w = (unsigned char)v3;
    }
    *(uint4*)(g_y8t + (size_t)(n0 + n) * MDIM + k0 + kc * 16) = *(uint4*)o;
    atomicAdd(&g_colsum[n0 + n], (float)part);
}

// ---------------------------------------------------------------------------
// Hybrid GEMM: persistent workers, CTA tile 128x64, 256 thr / 8 warps:
//   warps 0..3 : mma.sync, warp tile 32x32, cols [0,32)   (1 per SMSP)
//   warps 4..7 : dp4a,     warp tile 32x32, cols [32,64)  (1 per SMSP)
// BK=128 per step, 3 stages, one cp.async group per step, 2 CTAs/SM.
// ---------------------------------------------------------------------------
__global__ __launch_bounds__(256, 2) void gemm_kernel(float* __restrict__ out,
                                                      int nworkers) {
    extern __shared__ __align__(128) char smem[];
    const uint32_t sbase = smem_u32(smem);
    const int tid = threadIdx.x, lane = tid & 31, wid = tid >> 5;
    const int worker = blockIdx.x;

    const int cnt = (worker < NTILES) ? (NTILES - 1 - worker) / nworkers + 1 : 0;
    const int total = cnt * KITER;
    if (total == 0) return;

    // loader mapping: 192 rows x 8 x 16B = 1536 chunks, 6 per thread
    const int lrow = tid >> 3, lch = (tid & 7) * 16;  // 32 rows per pass

    auto load_g = [&](int g) {
        int t = worker + (g >> 5) * nworkers;
        int kt = g & (KITER - 1);
        const char* gA = g_x8  + (size_t)((t >> 6) * BM) * MDIM + kt * BK;
        const char* gB = g_y8t + (size_t)((t & (NT_N - 1)) * BN) * MDIM + kt * BK;
        uint32_t sA = sbase + (g % 3) * STAGE_BYTES;
        uint32_t sB = sA + A_STAGE;
#pragma unroll
        for (int q = 0; q < 4; q++) {  // A: 128 rows
            int row = lrow + q * 32;
            cp_async16(sA + row * ROWB + lch, gA + (size_t)row * MDIM + lch);
        }
#pragma unroll
        for (int q = 0; q < 2; q++) {  // B: 64 rows
            int row = lrow + q * 32;
            cp_async16(sB + row * ROWB + lch, gB + (size_t)row * MDIM + lch);
        }
    };

    // ---- role split: wid 0..3 tensor, wid 4..7 dp4a (1 of each per SMSP) --
    const bool is_tensor = (wid < 4);

    // Tensor warps: 4 m-blocks of 32 rows, cols [0,32)
    const int wm = wid * 32;
    const int rA = (lane & 7) + ((lane >> 3) & 1) * 8;
    const int cA = (lane >> 4) * 16;
    const int rB = (lane & 7) + (lane >> 4) * 8;
    const int cB = ((lane >> 3) & 1) * 16;

    // dp4a warps: dwid 0..3 -> rows dwid*32, cols [32,64)
    const int dwid = wid - 4;
    const int rg = lane >> 2;                     // 0..7 ; rows rg + 8i
    const int cg = lane & 3;                      // 0..3 ; cols cg + 4j

    int acc[2][4][4];                // tensor accumulators (2m x 4n frags)
    int dacc[4][8];                  // dp4a accumulators (4 rows x 8 cols)
#pragma unroll
    for (int i = 0; i < 2; i++)
#pragma unroll
        for (int j = 0; j < 4; j++)
#pragma unroll
            for (int v = 0; v < 4; v++) acc[i][j][v] = 0;
#pragma unroll
    for (int i = 0; i < 4; i++)
#pragma unroll
        for (int j = 0; j < 8; j++) dacc[i][j] = 0;

    // Epilogue constants:
    // out = S*P + S*(128-yz)*rowsum_x[m] - S*xz*colsum_shift[n] + S*K*xz*(yz-128)
    constexpr double Sd = X_SCALE * Y_SCALE;
    const float Sc     = (float)Sd;
    const float Crow   = (float)(Sd * (128.0 - Y_ZP));
    const float Ccol   = (float)(-Sd * X_ZP);
    const float Cconst = (float)(Sd * (double)MDIM * X_ZP * (Y_ZP - 128.0));
    const int rr = lane >> 2, cc = (lane & 3) * 2;

#pragma unroll
    for (int g = 0; g < STAGES - 1; g++) { load_g(g); CP_COMMIT(); }

    uint32_t a[2][2][4], b[2][2][4];  // tensor ping-pong fragments

#pragma unroll 1
    for (int g = 0; g < total; ++g) {
        CP_WAIT1();
        __syncthreads();
        if (g + 2 < total) load_g(g + 2);
        CP_COMMIT();

        const uint32_t stg = sbase + (g % 3) * STAGE_BYTES;
        const bool last_k = (g & (KITER - 1)) == KITER - 1;
        int t = worker + (g >> 5) * nworkers;
        int m0 = (t >> 6) * BM, n0 = (t & (NT_N - 1)) * BN;

        if (is_tensor) {
            // ---------------- tensor path: 32x32 x k128 ----------------
            const uint32_t aW = stg + (wm + rA) * ROWB + cA;
            const uint32_t bW = stg + A_STAGE + rB * ROWB + cB;

            ldmatrix_x4(a[0][0], aW);
            ldmatrix_x4(a[0][1], aW + 16 * ROWB);
            ldmatrix_x4(b[0][0], bW);
            ldmatrix_x4(b[0][1], bW + 16 * ROWB);
#pragma unroll
            for (int ks = 0; ks < 4; ks++) {
                const int pp = ks & 1;
                if (ks < 3) {
                    const int np = pp ^ 1, off = (ks + 1) * 32;
                    ldmatrix_x4(a[np][0], aW + off);
                    ldmatrix_x4(a[np][1], aW + 16 * ROWB + off);
                    ldmatrix_x4(b[np][0], bW + off);
                    ldmatrix_x4(b[np][1], bW + 16 * ROWB + off);
                }
                mma_s8(acc[0][0], a[pp][0], b[pp][0] + 0);
                mma_s8(acc[0][1], a[pp][0], b[pp][0] + 2);
                mma_s8(acc[0][2], a[pp][0], b[pp][1] + 0);
                mma_s8(acc[0][3], a[pp][0], b[pp][1] + 2);
                mma_s8(acc[1][0], a[pp][1], b[pp][0] + 0);
                mma_s8(acc[1][1], a[pp][1], b[pp][0] + 2);
                mma_s8(acc[1][2], a[pp][1], b[pp][1] + 0);
                mma_s8(acc[1][3], a[pp][1], b[pp][1] + 2);
            }

            if (last_k) {
                float rowC[2][2], colC[4][2];
#pragma unroll
                for (int i = 0; i < 2; i++) {
                    int r = m0 + wm + i * 16 + rr;
                    rowC[i][0] = Crow * g_rowsum[r]     + Cconst;
                    rowC[i][1] = Crow * g_rowsum[r + 8] + Cconst;
                }
#pragma unroll
                for (int j = 0; j < 4; j++) {
                    int c = n0 + j * 8 + cc;
                    colC[j][0] = Ccol * g_colsum[c];
                    colC[j][1] = Ccol * g_colsum[c + 1];
                }
#pragma unroll
                for (int i = 0; i < 2; i++) {
#pragma unroll
                    for (int j = 0; j < 4; j++) {
                        size_t r = (size_t)(m0 + wm + i * 16 + rr);
                        size_t c = (size_t)(n0 + j * 8 + cc);
                        float2 v0, v1;
                        v0.x = Sc * (float)acc[i][j][0] + rowC[i][0] + colC[j][0];
                        v0.y = Sc * (float)acc[i][j][1] + rowC[i][0] + colC[j][1];
                        v1.x = Sc * (float)acc[i][j][2] + rowC[i][1] + colC[j][0];
                        v1.y = Sc * (float)acc[i][j][3] + rowC[i][1] + colC[j][1];
                        *(float2*)(out + r * MDIM + c)       = v0;
                        *(float2*)(out + (r + 8) * MDIM + c) = v1;
#pragma unroll
                        for (int v = 0; v < 4; v++) acc[i][j][v] = 0;
                    }
                }
            }
        } else {
            // ------------ dp4a path: 32 rows x 32 cols x k128 -----------
            const char* sA = smem + (g % 3) * STAGE_BYTES;
            const char* sB = sA + A_STAGE + BN_T * ROWB;  // cols 32..63
            const int rbase = dwid * 32 + rg;
#pragma unroll 2
            for (int kk = 0; kk < 8; kk++) {
                int4 av[4], bv[8];
#pragma unroll
                for (int i = 0; i < 4; i++)
                    av[i] = *(const int4*)(sA + (rbase + 8 * i) * ROWB + kk * 16);
#pragma unroll
                for (int j = 0; j < 8; j++)
                    bv[j] = *(const int4*)(sB + (cg + 4 * j) * ROWB + kk * 16);
#pragma unroll
                for (int i = 0; i < 4; i++)
#pragma unroll
                    for (int j = 0; j < 8; j++) {
                        int s = dacc[i][j];
                        s = __dp4a(av[i].x, bv[j].x, s);
                        s = __dp4a(av[i].y, bv[j].y, s);
                        s = __dp4a(av[i].z, bv[j].z, s);
                        s = __dp4a(av[i].w, bv[j].w, s);
                        dacc[i][j] = s;
                    }
            }

            if (last_k) {
#pragma unroll
                for (int i = 0; i < 4; i++) {
                    int r = m0 + dwid * 32 + rg + 8 * i;
                    float rc = Crow * g_rowsum[r] + Cconst;
#pragma unroll
                    for (int j = 0; j < 8; j++) {
                        int c = n0 + BN_T + cg + 4 * j;
                        out[(size_t)r * MDIM + c] =
                            Sc * (float)dacc[i][j] + rc + Ccol * g_colsum[c];
                        dacc[i][j] = 0;
                    }
                }
            }
        }
    }
}

// ---------------------------------------------------------------------------
// Launch
// ---------------------------------------------------------------------------
extern "C" void kernel_launch(void* const* d_in, const int* in_sizes, int n_in,
                              void* d_out, int out_size) {
    const float* x = (const float*)d_in[0];  // [M,K]
    const float* y = (const float*)d_in[1];  // [K,N]
    float* out = (float*)d_out;

    static int nworkers = 0;
    if (nworkers == 0) {
        int dev = 0, sms = 148;
        cudaGetDevice(&dev);
        cudaDeviceGetAttribute(&sms, cudaDevAttrMultiProcessorCount, dev);
        nworkers = sms * 2;  // 2 CTAs/SM
        cudaFuncSetAttribute(gemm_kernel,
                             cudaFuncAttributeMaxDynamicSharedMemorySize,
                             SMEM_TOTAL);
    }

    void* csym = nullptr;
    cudaGetSymbolAddress(&csym, g_colsum);
    cudaMemsetAsync(csym, 0, MDIM * sizeof(float), 0);

    convert_x_kernel<<<MDIM, 256>>>(x);
    transpose_y_kernel<<<dim3(MDIM / 64, MDIM / 64), 256>>>(y);
    gemm_kernel<<<nworkers, 256, SMEM_TOTAL>>>(out, nworkers);
}